// round 11
// baseline (speedup 1.0000x reference)
#include <cuda_runtime.h>
#include <cuda_bf16.h>
#include <math.h>
#include <stdint.h>

// ---------------- problem constants ----------------
#define TT  32      // timesteps
#define BB  64      // batch
#define HH  512     // hidden
#define EE  512     // embed
#define MLL 64      // encoder length
#define VV  32000   // vocab
#define NL  2       // lstm layers
#define KP  1536    // vocab split-bf16 K (3 x 512)
#define KR  3072    // cat2 split-bf16 K (3 x 1024)
#define KG  1536    // gate-half split-bf16 K (3 x 512)
#define LDA 40      // padded smem row (bf16 units)
#define NREC 128    // recurrence blocks (grid barrier population)
#define NGRID 148   // total persistent blocks (all co-resident)
#define ZR  32      // rnn_in K-split planes
#define ZG  8       // gate x-part K-split planes
#define ZH  2       // gate h-part K-split planes
#define NTILE_N 250          // 32000/128 vocab n-tiles
#define NT_TOT (TT * NTILE_N)  // 8000 vocab tiles (64 x 128 each)

// ---------------- persistent device state ----------------
__device__ float g_h[NL][BB][HH];
__device__ float g_c[NL][BB][HH];
__device__ float g_rp[ZR][BB][EE];            // rnn_in K-split partials
__device__ float g_gp[ZG][BB][4 * HH];        // gate x-part partials
__device__ float g_gh[NL][ZH][BB][4 * HH];    // gate h-part partials
__device__ __nv_bfloat16 g_A1[BB][KR];        // cat2 split [emb|ctx]
__device__ __nv_bfloat16 g_GAx[NL][BB][KG];   // gate x-input split per layer
__device__ __nv_bfloat16 g_GAh[NL][BB][KG];   // gate h-input split per layer
__device__ __nv_bfloat16 g_AOW[EE][KR];       // attn_out_W split
__device__ __nv_bfloat16 g_GWx[NL][4 * HH][KG];  // Wi_l split
__device__ __nv_bfloat16 g_GWh[NL][4 * HH][KG];  // Wh_l split
__device__ __nv_bfloat16 g_Ap[(size_t)TT * BB * KP];   // vocab A'
__device__ __nv_bfloat16 g_Wp[(size_t)VV * KP];        // vocab W'

// sync / queue state
__device__ unsigned g_barc;
__device__ volatile unsigned g_barg;
__device__ unsigned g_vtile;           // vocab tile queue head
__device__ volatile unsigned g_done;   // completed steps

__device__ __forceinline__ float sigf(float x) { return 1.0f / (1.0f + expf(-x)); }

__device__ __forceinline__ uint32_t smem_u32(const void* p) {
    uint32_t a;
    asm("{ .reg .u64 t; cvta.to.shared.u64 t, %1; cvt.u32.u64 %0, t; }" : "=r"(a) : "l"(p));
    return a;
}

__device__ __forceinline__ void bsplit(float v, __nv_bfloat16& hi, __nv_bfloat16& lo) {
    hi = __float2bfloat16_rn(v);
    lo = __float2bfloat16_rn(v - __bfloat162float(hi));
}

// named team barrier (128 threads)
__device__ __forceinline__ void tbar(int id) {
    asm volatile("bar.sync %0, 128;" :: "r"(id) : "memory");
}

// grid barrier over the recurrence halves of blocks 0..NREC-1
__device__ __forceinline__ void gridbar() {
    tbar(1);
    if (threadIdx.x == 0) {
        unsigned g = g_barg;
        __threadfence();
        if (atomicAdd(&g_barc, 1u) == NREC - 1) {
            g_barc = 0;
            __threadfence();
            g_barg = g + 1;
        } else {
            while (g_barg == g) {}
            __threadfence();
        }
    }
    tbar(1);
}

// ---------------- init: state copy + h split + queue reset ----------------
__global__ void k_init(const float* __restrict__ h0, const float* __restrict__ c0) {
    int i = blockIdx.x * 256 + threadIdx.x;
    if (i == 0) { g_vtile = 0; g_done = 0; }
    if (i < NL * BB * HH) {
        ((float*)g_h)[i] = h0[i];
        ((float*)g_c)[i] = c0[i];
        int l = i >> 15, r = i & 32767;
        int b = r >> 9, h = r & 511;
        __nv_bfloat16 hi, lo;
        bsplit(h0[i], hi, lo);
        g_GAh[l][b][h] = hi; g_GAh[l][b][512 + h] = hi; g_GAh[l][b][1024 + h] = lo;
    }
}

// ================= shared 4-warp GEMM worker =================
// team tile 64(M) x 128(N); warps 2x2 of 32x64. Single smem buffer +
// register prefetch. bias==nullptr -> fp32 partial store; else bias+store.
__device__ void team_gemm(const __nv_bfloat16* __restrict__ A, int lda,
                          const __nv_bfloat16* __restrict__ W, int ldw,
                          int n0, int c0, int nch,
                          float* __restrict__ Cout, long long ldc,
                          const float* __restrict__ bias,
                          int wtid, int barId,
                          __nv_bfloat16* sA, __nv_bfloat16* sB)
{
    int w = wtid >> 5, lane = wtid & 31;
    int wm = (w & 1) * 32, wn = (w >> 1) * 64;

    float acc[2][8][4];
    #pragma unroll
    for (int a = 0; a < 2; a++)
        #pragma unroll
        for (int b = 0; b < 8; b++)
            #pragma unroll
            for (int q = 0; q < 4; q++) acc[a][b][q] = 0.f;

    int ar = wtid >> 2;                 // 0..31
    int sg = (wtid & 3) * 8;            // k-seg offset (bf16)
    const __nv_bfloat16* Ab = A + (size_t)c0 * 32 + sg;
    const __nv_bfloat16* Wb = W + (size_t)c0 * 32 + sg;

    float4 ra0 = *(const float4*)(Ab + (size_t)ar * lda);
    float4 ra1 = *(const float4*)(Ab + (size_t)(ar + 32) * lda);
    float4 rb0 = *(const float4*)(Wb + (size_t)(n0 + ar) * ldw);
    float4 rb1 = *(const float4*)(Wb + (size_t)(n0 + ar + 32) * ldw);
    float4 rb2 = *(const float4*)(Wb + (size_t)(n0 + ar + 64) * ldw);
    float4 rb3 = *(const float4*)(Wb + (size_t)(n0 + ar + 96) * ldw);

    for (int c = 0; c < nch; c++) {
        *(float4*)&sA[ar * LDA + sg]        = ra0;
        *(float4*)&sA[(ar + 32) * LDA + sg] = ra1;
        *(float4*)&sB[ar * LDA + sg]        = rb0;
        *(float4*)&sB[(ar + 32) * LDA + sg] = rb1;
        *(float4*)&sB[(ar + 64) * LDA + sg] = rb2;
        *(float4*)&sB[(ar + 96) * LDA + sg] = rb3;
        if (c + 1 < nch) {
            int o = (c + 1) * 32;
            ra0 = *(const float4*)(Ab + (size_t)ar * lda + o);
            ra1 = *(const float4*)(Ab + (size_t)(ar + 32) * lda + o);
            rb0 = *(const float4*)(Wb + (size_t)(n0 + ar) * ldw + o);
            rb1 = *(const float4*)(Wb + (size_t)(n0 + ar + 32) * ldw + o);
            rb2 = *(const float4*)(Wb + (size_t)(n0 + ar + 64) * ldw + o);
            rb3 = *(const float4*)(Wb + (size_t)(n0 + ar + 96) * ldw + o);
        }
        tbar(barId);

        #pragma unroll
        for (int ks = 0; ks < 2; ks++) {
            int kc = ks * 16;
            uint32_t afr[2][4];
            #pragma unroll
            for (int am = 0; am < 2; am++) {
                int row = wm + am * 16 + (lane & 15);
                int col = kc + (lane >> 4) * 8;
                uint32_t addr = smem_u32(&sA[row * LDA + col]);
                asm volatile("ldmatrix.sync.aligned.m8n8.x4.shared.b16 {%0,%1,%2,%3}, [%4];"
                    : "=r"(afr[am][0]), "=r"(afr[am][1]), "=r"(afr[am][2]), "=r"(afr[am][3])
                    : "r"(addr));
            }
            uint32_t bfr[4][4];
            #pragma unroll
            for (int bn = 0; bn < 4; bn++) {
                int sub = lane >> 3;
                int row = wn + bn * 16 + (sub >> 1) * 8 + (lane & 7);
                int col = kc + (sub & 1) * 8;
                uint32_t addr = smem_u32(&sB[row * LDA + col]);
                asm volatile("ldmatrix.sync.aligned.m8n8.x4.shared.b16 {%0,%1,%2,%3}, [%4];"
                    : "=r"(bfr[bn][0]), "=r"(bfr[bn][1]), "=r"(bfr[bn][2]), "=r"(bfr[bn][3])
                    : "r"(addr));
            }
            #pragma unroll
            for (int am = 0; am < 2; am++) {
                #pragma unroll
                for (int bn = 0; bn < 8; bn++) {
                    uint32_t b0 = bfr[bn >> 1][(bn & 1) * 2];
                    uint32_t b1 = bfr[bn >> 1][(bn & 1) * 2 + 1];
                    asm volatile(
                        "mma.sync.aligned.m16n8k16.row.col.f32.bf16.bf16.f32 "
                        "{%0,%1,%2,%3}, {%4,%5,%6,%7}, {%8,%9}, {%0,%1,%2,%3};"
                        : "+f"(acc[am][bn][0]), "+f"(acc[am][bn][1]),
                          "+f"(acc[am][bn][2]), "+f"(acc[am][bn][3])
                        : "r"(afr[am][0]), "r"(afr[am][1]), "r"(afr[am][2]), "r"(afr[am][3]),
                          "r"(b0), "r"(b1));
                }
            }
        }
        tbar(barId);
    }

    int group = lane >> 2, tq = (lane & 3) * 2;
    #pragma unroll
    for (int am = 0; am < 2; am++) {
        #pragma unroll
        for (int bn = 0; bn < 8; bn++) {
            int r0 = wm + am * 16 + group;
            int cx = n0 + wn + bn * 8 + tq;
            float b0 = 0.f, b1 = 0.f;
            if (bias) { b0 = bias[cx]; b1 = bias[cx + 1]; }
            float2 v0 = { acc[am][bn][0] + b0, acc[am][bn][1] + b1 };
            float2 v1 = { acc[am][bn][2] + b0, acc[am][bn][3] + b1 };
            *(float2*)&Cout[(long long)r0 * ldc + cx]       = v0;
            *(float2*)&Cout[(long long)(r0 + 8) * ldc + cx] = v1;
        }
    }
}

// ================= recurrence phases (128 threads) =================

__device__ void ph_attn(int b, const int* __restrict__ tok,
                        const float* __restrict__ emb,
                        const float* __restrict__ attn_W,
                        const float* __restrict__ enc,
                        float* av, float* sc)
{
    int tid = threadIdx.x;
    int t = tok[b];
    const float* er = emb + (size_t)t * EE;
    for (int i = tid; i < EE; i += 128) {
        float v = er[i];
        av[i] = v;
        __nv_bfloat16 hi, lo;
        bsplit(v, hi, lo);
        g_A1[b][i] = hi; g_A1[b][1024 + i] = hi; g_A1[b][2048 + i] = lo;
    }
    const float* hr = &g_h[NL - 1][b][0];
    for (int i = tid; i < HH; i += 128) av[EE + i] = hr[i];
    tbar(1);

    int w = tid >> 5, lane = tid & 31;
    for (int m = w; m < MLL; m += 4) {
        const float* wr = attn_W + (size_t)m * (EE + HH);
        float s = 0.f;
        #pragma unroll 8
        for (int k = lane; k < EE + HH; k += 32) s = fmaf(av[k], wr[k], s);
        #pragma unroll
        for (int o = 16; o; o >>= 1) s += __shfl_xor_sync(0xffffffffu, s, o);
        if (lane == 0) sc[m] = s;
    }
    tbar(1);

    if (tid < 32) {
        float a0 = sc[tid], a1 = sc[tid + 32];
        float m = fmaxf(a0, a1);
        #pragma unroll
        for (int o = 16; o; o >>= 1) m = fmaxf(m, __shfl_xor_sync(0xffffffffu, m, o));
        float e0 = expf(a0 - m), e1 = expf(a1 - m);
        float s = e0 + e1;
        #pragma unroll
        for (int o = 16; o; o >>= 1) s += __shfl_xor_sync(0xffffffffu, s, o);
        float inv = 1.0f / s;
        sc[tid] = e0 * inv;
        sc[tid + 32] = e1 * inv;
    }
    tbar(1);

    for (int h = tid; h < HH; h += 128) {
        float acc = 0.f;
        #pragma unroll 8
        for (int m = 0; m < MLL; m++)
            acc = fmaf(sc[m], enc[((size_t)m * BB + b) * HH + h], acc);
        __nv_bfloat16 hi, lo;
        bsplit(acc, hi, lo);
        g_A1[b][512 + h] = hi; g_A1[b][1536 + h] = hi; g_A1[b][2560 + h] = lo;
    }
    tbar(1);
}

__device__ void ph_comb(int bid) {
    const float* p = (const float*)g_rp;
    #pragma unroll
    for (int k = 0; k < 2; k++) {
        int i = bid * 128 + threadIdx.x + k * 16384;   // BB*EE = 32768
        int b = i >> 9, col = i & 511;
        float s = 0.f;
        #pragma unroll
        for (int q = 0; q < ZR; q++) s += p[(size_t)q * BB * EE + i];
        s = fmaxf(s, 0.0f);
        __nv_bfloat16 hi, lo;
        bsplit(s, hi, lo);
        g_GAx[0][b][col] = hi; g_GAx[0][b][512 + col] = hi; g_GAx[0][b][1024 + col] = lo;
    }
}

__device__ void ph_cell(int bid, int l, int t, const float* __restrict__ bi,
                        const float* __restrict__ bh) {
    #pragma unroll
    for (int k = 0; k < 2; k++) {
        int idx = bid * 128 + threadIdx.x + k * 16384;  // BB*HH
        int b = idx >> 9, h = idx & 511;
        float gi = 0.f, gf = 0.f, gg = 0.f, go = 0.f;
        #pragma unroll
        for (int s = 0; s < ZG; s++) {
            gi += g_gp[s][b][h];
            gf += g_gp[s][b][512 + h];
            gg += g_gp[s][b][1024 + h];
            go += g_gp[s][b][1536 + h];
        }
        #pragma unroll
        for (int s = 0; s < ZH; s++) {
            gi += g_gh[l][s][b][h];
            gf += g_gh[l][s][b][512 + h];
            gg += g_gh[l][s][b][1024 + h];
            go += g_gh[l][s][b][1536 + h];
        }
        const float* bip = bi + (size_t)l * 4 * HH;
        const float* bhp = bh + (size_t)l * 4 * HH;
        gi += bip[h]        + bhp[h];
        gf += bip[512 + h]  + bhp[512 + h];
        gg += bip[1024 + h] + bhp[1024 + h];
        go += bip[1536 + h] + bhp[1536 + h];

        float c  = g_c[l][b][h];
        float cn = sigf(gf) * c + sigf(gi) * tanhf(gg);
        float hn = sigf(go) * tanhf(cn);
        g_c[l][b][h] = cn;
        g_h[l][b][h] = hn;

        __nv_bfloat16 hi, lo;
        bsplit(hn, hi, lo);
        if (l == 0) {
            g_GAx[1][b][h] = hi; g_GAx[1][b][512 + h] = hi; g_GAx[1][b][1024 + h] = lo;
            g_GAh[0][b][h] = hi; g_GAh[0][b][512 + h] = hi; g_GAh[0][b][1024 + h] = lo;
        } else {
            g_GAh[1][b][h] = hi; g_GAh[1][b][512 + h] = hi; g_GAh[1][b][1024 + h] = lo;
            __nv_bfloat16* d = &g_Ap[(size_t)(t * BB + b) * KP];
            d[h] = hi; d[512 + h] = hi; d[1024 + h] = lo;
        }
    }
    __threadfence();   // order state writes before the grid barrier / g_done publish
}

// ================= vocab worker (warps 4-7 of every block) =================
__device__ void vocab_worker(const float* __restrict__ gen_b, float* __restrict__ out,
                             int wtid, __nv_bfloat16* sA, __nv_bfloat16* sB, int* sbc)
{
    for (;;) {
        if (wtid == 0) *sbc = (int)atomicAdd(&g_vtile, 1u);
        tbar(2);
        int v = *sbc;
        tbar(2);
        if (v >= NT_TOT) return;
        int t = v / NTILE_N;
        int nt = v - t * NTILE_N;
        if (wtid == 0) {
            while (g_done <= (unsigned)t) __nanosleep(128);
        }
        tbar(2);
        team_gemm(g_Ap + (size_t)t * 64 * KP, KP, g_Wp, KP,
                  nt * 128, 0, KP / 32,
                  out + (size_t)(t * 64) * VV, VV, gen_b,
                  wtid, 2, sA, sB);
    }
}

// ================= the persistent kernel =================
__global__ void __launch_bounds__(256) k_rec(
    const int* __restrict__ cur, const int* __restrict__ gtr,
    const float* __restrict__ emb, const float* __restrict__ attn_W,
    const float* __restrict__ enc, const float* __restrict__ bi,
    const float* __restrict__ bh,
    const float* __restrict__ gen_b, float* __restrict__ out)
{
    __shared__ __align__(16) __nv_bfloat16 sAr[64 * LDA];
    __shared__ __align__(16) __nv_bfloat16 sBr[128 * LDA];
    __shared__ __align__(16) __nv_bfloat16 sAv[64 * LDA];
    __shared__ __align__(16) __nv_bfloat16 sBv[128 * LDA];
    __shared__ int sbc;

    int tid = threadIdx.x, bid = blockIdx.x;

    if (tid >= 128) {               // vocab team: all blocks
        vocab_worker(gen_b, out, tid - 128, sAv, sBv, &sbc);
        return;
    }
    if (bid >= NREC) return;        // recurrence only on blocks 0..127

    for (int t = 0; t < TT; t++) {
        const int* tok = (t == 0) ? cur : (gtr + (size_t)(t - 1) * BB);
        // P1: attention (0-63) || gate h-part GEMMs (64-127)
        if (bid < 64) {
            ph_attn(bid, tok, emb, attn_W, enc, (float*)sAr, (float*)sAr + 2 * EE);
        } else {
            int q = bid - 64;
            int l = q >> 5, s = q & 31;
            int nt = s & 15, z = s >> 4;
            team_gemm(&g_GAh[l][0][0], KG, &g_GWh[l][0][0], KG,
                      nt * 128, z * 24, 24,
                      &g_gh[l][z][0][0], 4 * HH, nullptr, tid, 1, sAr, sBr);
        }
        gridbar();
        // P2: rnn_in
        {
            int nt = bid & 3, z = bid >> 2;
            team_gemm(&g_A1[0][0], KR, &g_AOW[0][0], KR,
                      nt * 128, z * 3, 3,
                      &g_rp[z][0][0], EE, nullptr, tid, 1, sAr, sBr);
        }
        gridbar();
        ph_comb(bid);
        gridbar();
        // P4: gates l0 x-part
        {
            int nt = bid & 15, z = bid >> 4;
            team_gemm(&g_GAx[0][0][0], KG, &g_GWx[0][0][0], KG,
                      nt * 128, z * 6, 6,
                      &g_gp[z][0][0], 4 * HH, nullptr, tid, 1, sAr, sBr);
        }
        gridbar();
        ph_cell(bid, 0, t, bi, bh);
        gridbar();
        // P6: gates l1 x-part
        {
            int nt = bid & 15, z = bid >> 4;
            team_gemm(&g_GAx[1][0][0], KG, &g_GWx[1][0][0], KG,
                      nt * 128, z * 6, 6,
                      &g_gp[z][0][0], 4 * HH, nullptr, tid, 1, sAr, sBr);
        }
        gridbar();
        ph_cell(bid, 1, t, bi, bh);
        gridbar();
        if (bid == 0 && tid == 0) {
            __threadfence();
            g_done = t + 1;      // unlock this step's vocab tiles
        }
    }
}

// ---------------- one-time weight splits ----------------
__global__ void __launch_bounds__(256) k_cvtW(const float* __restrict__ W) {
    size_t t = (size_t)blockIdx.x * 256 + threadIdx.x;   // VV*512/4
    size_t row = t >> 7;
    int kq = (int)(t & 127) * 4;
    float4 v = *(const float4*)(W + row * 512 + kq);
    __nv_bfloat16 h0, l0, h1, l1, h2, l2, h3, l3;
    bsplit(v.x, h0, l0); bsplit(v.y, h1, l1); bsplit(v.z, h2, l2); bsplit(v.w, h3, l3);
    __nv_bfloat16* d = &g_Wp[row * KP + kq];
    *(__nv_bfloat162*)(d)        = __nv_bfloat162(h0, h1);
    *(__nv_bfloat162*)(d + 2)    = __nv_bfloat162(h2, h3);
    *(__nv_bfloat162*)(d + 512)  = __nv_bfloat162(l0, l1);
    *(__nv_bfloat162*)(d + 514)  = __nv_bfloat162(l2, l3);
    *(__nv_bfloat162*)(d + 1024) = __nv_bfloat162(h0, h1);
    *(__nv_bfloat162*)(d + 1026) = __nv_bfloat162(h2, h3);
}

__global__ void __launch_bounds__(256) k_cvtGW(const float* __restrict__ Wi,
                                               const float* __restrict__ Wh) {
    size_t t = (size_t)blockIdx.x * 256 + threadIdx.x;   // NL*2048*128
    if (t >= (size_t)NL * 4 * HH * 128) return;
    int l = (int)(t >> 18);
    size_t r = t & ((1u << 18) - 1);
    int n = (int)(r >> 7);
    int k = (int)(r & 127) * 4;

    float4 v = *(const float4*)(Wi + ((size_t)l * 4 * HH + n) * 512 + k);
    __nv_bfloat16 h0, l0, h1, l1, h2, l2, h3, l3;
    bsplit(v.x, h0, l0); bsplit(v.y, h1, l1); bsplit(v.z, h2, l2); bsplit(v.w, h3, l3);
    __nv_bfloat16* d = &g_GWx[l][n][k];
    *(__nv_bfloat162*)(d)        = __nv_bfloat162(h0, h1);
    *(__nv_bfloat162*)(d + 2)    = __nv_bfloat162(h2, h3);
    *(__nv_bfloat162*)(d + 512)  = __nv_bfloat162(l0, l1);
    *(__nv_bfloat162*)(d + 514)  = __nv_bfloat162(l2, l3);
    *(__nv_bfloat162*)(d + 1024) = __nv_bfloat162(h0, h1);
    *(__nv_bfloat162*)(d + 1026) = __nv_bfloat162(h2, h3);

    v = *(const float4*)(Wh + ((size_t)l * 4 * HH + n) * 512 + k);
    bsplit(v.x, h0, l0); bsplit(v.y, h1, l1); bsplit(v.z, h2, l2); bsplit(v.w, h3, l3);
    d = &g_GWh[l][n][k];
    *(__nv_bfloat162*)(d)        = __nv_bfloat162(h0, h1);
    *(__nv_bfloat162*)(d + 2)    = __nv_bfloat162(h2, h3);
    *(__nv_bfloat162*)(d + 512)  = __nv_bfloat162(l0, l1);
    *(__nv_bfloat162*)(d + 514)  = __nv_bfloat162(l2, l3);
    *(__nv_bfloat162*)(d + 1024) = __nv_bfloat162(h0, h1);
    *(__nv_bfloat162*)(d + 1026) = __nv_bfloat162(h2, h3);
}

__global__ void __launch_bounds__(256) k_cvtAOW(const float* __restrict__ W) {
    size_t t = (size_t)blockIdx.x * 256 + threadIdx.x;
    if (t >= (size_t)EE * 1024 / 4) return;
    int row = (int)(t >> 8);
    int k = (int)(t & 255) * 4;
    float4 v = *(const float4*)(W + (size_t)row * 1024 + k);
    __nv_bfloat16 h0, l0, h1, l1, h2, l2, h3, l3;
    bsplit(v.x, h0, l0); bsplit(v.y, h1, l1); bsplit(v.z, h2, l2); bsplit(v.w, h3, l3);
    __nv_bfloat16* d = &g_AOW[row][k];
    *(__nv_bfloat162*)(d)        = __nv_bfloat162(h0, h1);
    *(__nv_bfloat162*)(d + 2)    = __nv_bfloat162(h2, h3);
    *(__nv_bfloat162*)(d + 1024) = __nv_bfloat162(l0, l1);
    *(__nv_bfloat162*)(d + 1026) = __nv_bfloat162(l2, l3);
    *(__nv_bfloat162*)(d + 2048) = __nv_bfloat162(h0, h1);
    *(__nv_bfloat162*)(d + 2050) = __nv_bfloat162(h2, h3);
}

// ---------------- final state copy ----------------
__global__ void k_fin(float* __restrict__ out) {
    int i = blockIdx.x * 256 + threadIdx.x;
    int n = NL * BB * HH;
    if (i < n)           out[i] = ((const float*)g_h)[i];
    else if (i < 2 * n)  out[i] = ((const float*)g_c)[i - n];
}

// ---------------- launch ----------------
extern "C" void kernel_launch(void* const* d_in, const int* in_sizes, int n_in,
                              void* d_out, int out_size) {
    int o = (n_in >= 15) ? 1 : 0;   // optional scalar 'length'
    const int*   cur        = (const int*)  d_in[0];
    const float* h0         = (const float*)d_in[1];
    const float* c0         = (const float*)d_in[2];
    const float* enc        = (const float*)d_in[3];
    const int*   gtr        = (const int*)  d_in[4];
    const float* emb        = (const float*)d_in[5 + o];
    const float* attn_W     = (const float*)d_in[6 + o];
    const float* attn_out_W = (const float*)d_in[7 + o];
    const float* Wi         = (const float*)d_in[8 + o];
    const float* Wh         = (const float*)d_in[9 + o];
    const float* bi         = (const float*)d_in[10 + o];
    const float* bh         = (const float*)d_in[11 + o];
    const float* gen_W      = (const float*)d_in[12 + o];
    const float* gen_b      = (const float*)d_in[13 + o];
    float* out = (float*)d_out;

    k_init<<<(NL * BB * HH + 255) / 256, 256>>>(h0, c0);
    k_cvtW<<<(VV * 512 / 4 + 255) / 256, 256>>>(gen_W);
    k_cvtGW<<<((NL * 4 * HH * 128) + 255) / 256, 256>>>(Wi, Wh);
    k_cvtAOW<<<((EE * 1024 / 4) + 255) / 256, 256>>>(attn_out_W);

    // recurrence + fully-overlapped vocab GEMM in one persistent kernel
    k_rec<<<NGRID, 256>>>(cur, gtr, emb, attn_W, enc, bi, bh, gen_b, out);

    size_t sn = (size_t)TT * BB * VV;
    if ((size_t)out_size >= sn + (size_t)2 * NL * BB * HH)
        k_fin<<<(2 * NL * BB * HH + 255) / 256, 256>>>(out + sn);
}